// round 2
// baseline (speedup 1.0000x reference)
#include <cuda_runtime.h>
#include <math.h>

#define NBLK 3
#define BD 8
#define HWQ 4096   // 64*64
#define NCH 64     // NC (channels per DAT block)
#define NS  256    // Hk*Wk = 16*16
#define HCD 16     // head channels
#define TABN 16129 // 127*127
#define TABPAD 16272

// ---- static device scratch (no runtime allocation allowed) ----
__device__ float  g_Q[NBLK*BD*NCH*HWQ];   // q projections      [blk][b][c][hw]
__device__ float  g_O[NBLK*BD*NCH*HWQ];   // attention outputs  [blk][b][c][hw]
__device__ float  g_K[NBLK*BD*NCH*NS];    // keys   [blk][b][c][n]
__device__ float  g_V[NBLK*BD*NCH*NS];    // values [blk][b][c][n]
__device__ float4 g_BP[NBLK*BD*NS];       // bias params per n: (y0*127+x0, wy, wx, 0)

// ============================================================================
// Kernel A: q = pq_w @ x[:, :64] + pq_b      (3 blocks; blk0<-x1, blk1/2<-x2)
// grid = 96 (3 blk * 8 b * 4 hw-tiles of 1024), 256 threads, 4 hw per thread
// ============================================================================
__global__ __launch_bounds__(256) void k_qproj(
    const float* __restrict__ x1, const float* __restrict__ x2,
    const float* __restrict__ pqw, const float* __restrict__ pqb)
{
    __shared__ float wsT[64*64];  // wsT[c][o] = w[o][c]
    __shared__ float bs[64];
    int bx = blockIdx.x;
    int tile = bx & 3, b = (bx >> 2) & 7, blk = bx >> 5;
    const float* xin = (blk == 0 ? x1 : x2) + (size_t)b * 128 * HWQ;

    for (int i = threadIdx.x; i < 4096; i += 256) {
        int c = i >> 6, o = i & 63;
        wsT[c*64 + o] = pqw[blk*4096 + o*64 + c];
    }
    if (threadIdx.x < 64) bs[threadIdx.x] = pqb[blk*64 + threadIdx.x];
    __syncthreads();

    int hw = tile*1024 + threadIdx.x*4;
    float* qout = g_Q + (size_t)(blk*BD + b) * NCH * HWQ;

    for (int g = 0; g < 4; ++g) {
        float4 acc[16];
        #pragma unroll
        for (int cc = 0; cc < 16; ++cc) {
            float bb = bs[g*16 + cc];
            acc[cc] = make_float4(bb, bb, bb, bb);
        }
        #pragma unroll 4
        for (int c = 0; c < 64; ++c) {
            float4 xv = *reinterpret_cast<const float4*>(xin + c*HWQ + hw);
            #pragma unroll
            for (int cc = 0; cc < 16; ++cc) {
                float wv = wsT[c*64 + g*16 + cc];
                acc[cc].x = fmaf(wv, xv.x, acc[cc].x);
                acc[cc].y = fmaf(wv, xv.y, acc[cc].y);
                acc[cc].z = fmaf(wv, xv.z, acc[cc].z);
                acc[cc].w = fmaf(wv, xv.w, acc[cc].w);
            }
        }
        #pragma unroll
        for (int cc = 0; cc < 16; ++cc)
            *reinterpret_cast<float4*>(qout + (g*16 + cc)*HWQ + hw) = acc[cc];
    }
}

// ============================================================================
// Kernel BC: offset head (dwconv4s4 -> LN -> GELU -> 1x1 -> 2ch) -> pos ->
//            deformable gather of kv -> k/v projections + bias params.
// grid = 24 (blk,b), 256 threads = one per key point n=(oy,ox)
// dynamic smem: buf[256][65] + pk_w[4096] + pv_w[4096]
// ============================================================================
__global__ __launch_bounds__(256) void k_offkv(
    const float* __restrict__ x0, const float* __restrict__ x1,
    const float* __restrict__ dww, const float* __restrict__ dwb,
    const float* __restrict__ lng, const float* __restrict__ lnb,
    const float* __restrict__ pww,
    const float* __restrict__ pkw, const float* __restrict__ pkb,
    const float* __restrict__ pvw, const float* __restrict__ pvb)
{
    extern __shared__ float sm[];
    float* buf = sm;              // [256][65] (pad 65 -> conflict-free per-row)
    float* skw = sm + 256*65;     // 4096
    float* svw = skw + 4096;      // 4096

    int bx = blockIdx.x;
    int b = bx & 7, blk = bx >> 3;
    const float* kvsrc = (blk == 2 ? x1 : x0) + (size_t)b * 128 * HWQ;
    const float* qsrc  = g_Q + (size_t)(blk*BD + b) * NCH * HWQ;
    int tid = threadIdx.x;

    for (int i = tid; i < 4096; i += 256) {
        skw[i] = pkw[blk*4096 + i];
        svw[i] = pvw[blk*4096 + i];
    }
    __syncthreads();

    int oy = tid >> 4, ox = tid & 15;

    // --- phase 1: depthwise conv 4x4 stride 4 (VALID) on q plane ---
    float s1 = 0.f, s2 = 0.f;
    const float* wdw = dww + blk * NCH * 16;
    for (int c = 0; c < 64; ++c) {
        float a = __ldg(&dwb[blk*64 + c]);
        const float* qp = qsrc + c*HWQ + (oy*4)*64 + ox*4;
        #pragma unroll
        for (int ky = 0; ky < 4; ++ky)
            #pragma unroll
            for (int kx = 0; kx < 4; ++kx)
                a = fmaf(qp[ky*64 + kx], __ldg(&wdw[c*16 + ky*4 + kx]), a);
        buf[tid*65 + c] = a;
        s1 += a; s2 += a*a;
    }
    float mu  = s1 * (1.f/64.f);
    float var = s2 * (1.f/64.f) - mu*mu;
    float rs  = rsqrtf(var + 1e-5f);

    // --- LN -> exact GELU -> 1x1 to 2 channels (y,x offset) ---
    float offy = 0.f, offx = 0.f;
    for (int c = 0; c < 64; ++c) {
        float v = (buf[tid*65 + c] - mu) * rs * __ldg(&lng[blk*64 + c]) + __ldg(&lnb[blk*64 + c]);
        float gl = 0.5f * v * (1.f + erff(v * 0.70710678118654752f));
        offy = fmaf(__ldg(&pww[blk*128 + c]),      gl, offy);
        offx = fmaf(__ldg(&pww[blk*128 + 64 + c]), gl, offx);
    }
    float refy = (2.f*((float)oy + 0.5f)) * (1.f/15.f) - 1.f;
    float refx = (2.f*((float)ox + 0.5f)) * (1.f/15.f) - 1.f;
    float py = fminf(fmaxf(offy + refy, -1.f), 1.f);
    float px = fminf(fmaxf(offx + refx, -1.f), 1.f);

    // --- bias bilinear params (separable trick: weights depend only on n) ---
    float ay = 31.5f*(1.f - py), ax = 31.5f*(1.f - px);
    float by0 = floorf(ay), bx0 = floorf(ax);
    g_BP[(blk*BD + b)*NS + tid] = make_float4(by0*127.f + bx0, ay - by0, ax - bx0, 0.f);

    // --- deformable bilinear gather of kv at pos (align_corners=True) ---
    float sy = (py + 1.f)*31.5f, sx = (px + 1.f)*31.5f;
    float fy = floorf(sy), fx = floorf(sx);
    int iy0 = (int)fy, ix0 = (int)fx;
    float wby = sy - fy, wbx = sx - fx;
    int iy1 = min(iy0 + 1, 63), ix1 = min(ix0 + 1, 63);
    float w00 = (1.f-wby)*(1.f-wbx), w01 = (1.f-wby)*wbx;
    float w10 = wby*(1.f-wbx),       w11 = wby*wbx;
    for (int c = 0; c < 64; ++c) {
        const float* ip = kvsrc + c*HWQ;
        float v = w00*ip[iy0*64 + ix0] + w01*ip[iy0*64 + ix1]
                + w10*ip[iy1*64 + ix0] + w11*ip[iy1*64 + ix1];
        buf[tid*65 + c] = v;   // per-thread private row; no cross-thread use
    }

    // --- k/v projections (per-n GEMV, weights broadcast from smem) ---
    float* kout = g_K + (size_t)(blk*BD + b) * NCH * NS;
    float* vout = g_V + (size_t)(blk*BD + b) * NCH * NS;
    for (int o = 0; o < 64; ++o) {
        float ak = __ldg(&pkb[blk*64 + o]);
        float av = __ldg(&pvb[blk*64 + o]);
        #pragma unroll 8
        for (int c = 0; c < 64; ++c) {
            float xv = buf[tid*65 + c];
            ak = fmaf(skw[o*64 + c], xv, ak);
            av = fmaf(svw[o*64 + c], xv, av);
        }
        kout[o*NS + tid] = ak;
        vout[o*NS + tid] = av;
    }
}

// ============================================================================
// Kernel D: attention. One CTA per (blk,b,head,m-tile of 256). 256 threads,
// one query row m per thread, flash-style n-loop (no-max exp: logits bounded).
// dynamic smem: rpe table (padded) + K[n][16] + V[n][16] + bias params
// ============================================================================
__global__ __launch_bounds__(256, 2) void k_attn(const float* __restrict__ rpe)
{
    extern __shared__ float sm[];
    float*  tab   = sm;                          // TABPAD
    float*  Ks    = sm + TABPAD;                 // 256*16, [n][c]
    float*  Vs    = Ks + 4096;                   // 256*16
    int*    pbase = (int*)(Vs + 4096);           // 256
    float4* pw4   = (float4*)(pbase + 256);      // 256

    int bx = blockIdx.x;
    int mt = bx & 15, head = (bx >> 4) & 3, bb = bx >> 6;  // bb = blk*8+b
    int tid = threadIdx.x;

    // load per-head RPE table (zero-pad the tail so weight-0 taps read 0)
    const float* tsrc = rpe + (size_t)((bb >> 3)*4 + head) * TABN;
    for (int i = tid; i < TABPAD; i += 256)
        tab[i] = (i < TABN) ? tsrc[i] : 0.f;

    // K/V head slices -> [n][c] float4-friendly layout
    const float* kg = g_K + (size_t)(bb*NCH + head*HCD) * NS;
    const float* vg = g_V + (size_t)(bb*NCH + head*HCD) * NS;
    #pragma unroll
    for (int c4 = 0; c4 < 4; ++c4) {
        float a0 = kg[(c4*4+0)*NS + tid], a1 = kg[(c4*4+1)*NS + tid];
        float a2 = kg[(c4*4+2)*NS + tid], a3 = kg[(c4*4+3)*NS + tid];
        reinterpret_cast<float4*>(Ks)[tid*4 + c4] = make_float4(a0,a1,a2,a3);
        a0 = vg[(c4*4+0)*NS + tid]; a1 = vg[(c4*4+1)*NS + tid];
        a2 = vg[(c4*4+2)*NS + tid]; a3 = vg[(c4*4+3)*NS + tid];
        reinterpret_cast<float4*>(Vs)[tid*4 + c4] = make_float4(a0,a1,a2,a3);
    }
    {
        float4 bp = g_BP[bb*NS + tid];
        pbase[tid] = (int)bp.x;
        float wy = bp.y, wx = bp.z;
        pw4[tid] = make_float4((1.f-wy)*(1.f-wx), (1.f-wy)*wx, wy*(1.f-wx), wy*wx);
    }
    __syncthreads();

    int m = mt*256 + tid;
    int rbase = (m >> 6)*127 + (m & 63);
    const float* qg = g_Q + (size_t)(bb*NCH + head*HCD) * HWQ + m;
    float q[16];
    #pragma unroll
    for (int c = 0; c < 16; ++c) q[c] = qg[c*HWQ];

    float acc[16];
    #pragma unroll
    for (int c = 0; c < 16; ++c) acc[c] = 0.f;
    float ssum = 0.f;

    const float4* Ks4 = (const float4*)Ks;
    const float4* Vs4 = (const float4*)Vs;

    #pragma unroll 4
    for (int n = 0; n < 256; ++n) {
        int o = pbase[n] + rbase;
        float4 w = pw4[n];
        float bias =        w.x * tab[o];
        bias = fmaf(w.y, tab[o+1],   bias);
        bias = fmaf(w.z, tab[o+127], bias);
        bias = fmaf(w.w, tab[o+128], bias);

        float4 k0 = Ks4[n*4+0], k1 = Ks4[n*4+1], k2 = Ks4[n*4+2], k3 = Ks4[n*4+3];
        float d0 = q[0]*k0.x;  d0 = fmaf(q[1], k0.y, d0);
        d0 = fmaf(q[2], k0.z, d0);  d0 = fmaf(q[3],  k0.w, d0);
        d0 = fmaf(q[4], k1.x, d0);  d0 = fmaf(q[5],  k1.y, d0);
        d0 = fmaf(q[6], k1.z, d0);  d0 = fmaf(q[7],  k1.w, d0);
        float d1 = q[8]*k2.x;  d1 = fmaf(q[9], k2.y, d1);
        d1 = fmaf(q[10], k2.z, d1); d1 = fmaf(q[11], k2.w, d1);
        d1 = fmaf(q[12], k3.x, d1); d1 = fmaf(q[13], k3.y, d1);
        d1 = fmaf(q[14], k3.z, d1); d1 = fmaf(q[15], k3.w, d1);

        float p = __expf(fmaf(d0 + d1, 0.25f, bias));
        ssum += p;

        float4 v0 = Vs4[n*4+0], v1 = Vs4[n*4+1], v2 = Vs4[n*4+2], v3 = Vs4[n*4+3];
        acc[0]  = fmaf(p, v0.x, acc[0]);  acc[1]  = fmaf(p, v0.y, acc[1]);
        acc[2]  = fmaf(p, v0.z, acc[2]);  acc[3]  = fmaf(p, v0.w, acc[3]);
        acc[4]  = fmaf(p, v1.x, acc[4]);  acc[5]  = fmaf(p, v1.y, acc[5]);
        acc[6]  = fmaf(p, v1.z, acc[6]);  acc[7]  = fmaf(p, v1.w, acc[7]);
        acc[8]  = fmaf(p, v2.x, acc[8]);  acc[9]  = fmaf(p, v2.y, acc[9]);
        acc[10] = fmaf(p, v2.z, acc[10]); acc[11] = fmaf(p, v2.w, acc[11]);
        acc[12] = fmaf(p, v3.x, acc[12]); acc[13] = fmaf(p, v3.y, acc[13]);
        acc[14] = fmaf(p, v3.z, acc[14]); acc[15] = fmaf(p, v3.w, acc[15]);
    }

    float inv = 1.f / ssum;
    float* og = g_O + (size_t)(bb*NCH + head*HCD) * HWQ + m;
    #pragma unroll
    for (int c = 0; c < 16; ++c) og[c*HWQ] = acc[c] * inv;
}

// ============================================================================
// Kernel E: final assembly. out[l] = x_l; channels 64..127 += po conv of the
// attention outputs of this level's blocks (lvl1: blk0; lvl2: blk1+blk2).
// grid = 96 (3 lvl * 8 b * 4 hw-tiles of 1024), 256 threads, 4 hw per thread
// ============================================================================
__global__ __launch_bounds__(256) void k_out(
    const float* __restrict__ x0, const float* __restrict__ x1,
    const float* __restrict__ x2,
    const float* __restrict__ poww, const float* __restrict__ pob,
    float* __restrict__ out)
{
    __shared__ float wsT[2][64*64];  // transposed po weights, up to 2 blocks
    __shared__ float bsum[64];
    int bx = blockIdx.x;
    int tile = bx & 3, b = (bx >> 2) & 7, lvl = bx >> 5;
    const float* xl = (lvl == 0 ? x0 : (lvl == 1 ? x1 : x2)) + (size_t)b * 128 * HWQ;
    float* outp = out + (size_t)(lvl*BD + b) * 128 * HWQ;
    int hw = tile*1024 + threadIdx.x*4;

    // passthrough: channels 0..63
    for (int c = 0; c < 64; ++c)
        *reinterpret_cast<float4*>(outp + c*HWQ + hw) =
            *reinterpret_cast<const float4*>(xl + c*HWQ + hw);

    if (lvl == 0) {
        for (int c = 64; c < 128; ++c)
            *reinterpret_cast<float4*>(outp + c*HWQ + hw) =
                *reinterpret_cast<const float4*>(xl + c*HWQ + hw);
        return;
    }

    int blk0 = (lvl == 1) ? 0 : 1;
    int nb   = (lvl == 1) ? 1 : 2;

    for (int i = threadIdx.x; i < 4096; i += 256) {
        int c = i >> 6, o = i & 63;
        wsT[0][c*64 + o] = poww[blk0*4096 + o*64 + c];
        if (nb == 2) wsT[1][c*64 + o] = poww[(blk0+1)*4096 + o*64 + c];
    }
    if (threadIdx.x < 64) {
        float s = pob[blk0*64 + threadIdx.x];
        if (nb == 2) s += pob[(blk0+1)*64 + threadIdx.x];
        bsum[threadIdx.x] = s;
    }
    __syncthreads();

    const float* o0 = g_O + (size_t)(blk0*BD + b) * NCH * HWQ;
    const float* o1 = g_O + (size_t)((blk0+1)*BD + b) * NCH * HWQ;

    for (int g = 0; g < 4; ++g) {
        float4 acc[16];
        #pragma unroll
        for (int cc = 0; cc < 16; ++cc) {
            float4 xb = *reinterpret_cast<const float4*>(xl + (64 + g*16 + cc)*HWQ + hw);
            float bb = bsum[g*16 + cc];
            acc[cc] = make_float4(xb.x + bb, xb.y + bb, xb.z + bb, xb.w + bb);
        }
        #pragma unroll 2
        for (int c = 0; c < 64; ++c) {
            float4 a0 = *reinterpret_cast<const float4*>(o0 + c*HWQ + hw);
            #pragma unroll
            for (int cc = 0; cc < 16; ++cc) {
                float wv = wsT[0][c*64 + g*16 + cc];
                acc[cc].x = fmaf(wv, a0.x, acc[cc].x);
                acc[cc].y = fmaf(wv, a0.y, acc[cc].y);
                acc[cc].z = fmaf(wv, a0.z, acc[cc].z);
                acc[cc].w = fmaf(wv, a0.w, acc[cc].w);
            }
            if (nb == 2) {
                float4 a1 = *reinterpret_cast<const float4*>(o1 + c*HWQ + hw);
                #pragma unroll
                for (int cc = 0; cc < 16; ++cc) {
                    float wv = wsT[1][c*64 + g*16 + cc];
                    acc[cc].x = fmaf(wv, a1.x, acc[cc].x);
                    acc[cc].y = fmaf(wv, a1.y, acc[cc].y);
                    acc[cc].z = fmaf(wv, a1.z, acc[cc].z);
                    acc[cc].w = fmaf(wv, a1.w, acc[cc].w);
                }
            }
        }
        #pragma unroll
        for (int cc = 0; cc < 16; ++cc)
            *reinterpret_cast<float4*>(outp + (64 + g*16 + cc)*HWQ + hw) = acc[cc];
    }
}

// ============================================================================
extern "C" void kernel_launch(void* const* d_in, const int* in_sizes, int n_in,
                              void* d_out, int out_size)
{
    const float* x0  = (const float*)d_in[0];
    const float* x1  = (const float*)d_in[1];
    const float* x2  = (const float*)d_in[2];
    const float* pqw = (const float*)d_in[3];
    const float* pqb = (const float*)d_in[4];
    const float* dww = (const float*)d_in[5];
    const float* dwb = (const float*)d_in[6];
    const float* lng = (const float*)d_in[7];
    const float* lnb = (const float*)d_in[8];
    const float* pww = (const float*)d_in[9];
    const float* pkw = (const float*)d_in[10];
    const float* pkb = (const float*)d_in[11];
    const float* pvw = (const float*)d_in[12];
    const float* pvb = (const float*)d_in[13];
    const float* pow_ = (const float*)d_in[14];
    const float* pob = (const float*)d_in[15];
    const float* rpe = (const float*)d_in[16];

    const int bc_smem = (256*65 + 4096 + 4096) * 4;               // 99328 B
    const int d_smem  = (TABPAD + 4096 + 4096) * 4 + 256*4 + 256*16; // 102976 B
    cudaFuncSetAttribute(k_offkv, cudaFuncAttributeMaxDynamicSharedMemorySize, bc_smem);
    cudaFuncSetAttribute(k_attn,  cudaFuncAttributeMaxDynamicSharedMemorySize, d_smem);

    k_qproj<<<96, 256>>>(x1, x2, pqw, pqb);
    k_offkv<<<24, 256, bc_smem>>>(x0, x1, dww, dwb, lng, lnb, pww,
                                  pkw, pkb, pvw, pvb);
    k_attn<<<1536, 256, d_smem>>>(rpe);
    k_out<<<96, 256>>>(x0, x1, x2, pow_, pob, (float*)d_out);
}

// round 3
// speedup vs baseline: 1.0731x; 1.0731x over previous
#include <cuda_runtime.h>
#include <math.h>

#define NBLK 3
#define BD 8
#define HWQ 4096   // 64*64
#define NCH 64     // NC (channels per DAT block)
#define NS  256    // Hk*Wk = 16*16
#define HCD 16     // head channels
#define TABN 16129 // 127*127
#define TABP 16384 // padded table stride (global scratch)

// ---- static device scratch (no runtime allocation allowed) ----
__device__ float  g_Q[NBLK*BD*NCH*HWQ];   // q projections      [blk][b][c][hw]
__device__ float  g_O[NBLK*BD*NCH*HWQ];   // attention outputs  [blk][b][c][hw]
__device__ float  g_K[NBLK*BD*NCH*NS];    // keys   [blk][b][c][n]
__device__ float  g_V[NBLK*BD*NCH*NS];    // values [blk][b][c][n]
__device__ float4 g_BP[NBLK*BD*NS];       // bias params per n: (y0*127+x0, wy, wx, 0)
__device__ float  g_TAB[NBLK*4*TABP];     // zero-padded per-(blk,head) RPE tables

// ============================================================================
// Kernel T: pad-copy rpe tables into g_TAB. grid=48 (12 tables * 4 quarters)
// ============================================================================
__global__ __launch_bounds__(256) void k_tab(const float* __restrict__ rpe)
{
    int t = blockIdx.x >> 2, q = blockIdx.x & 3;
    const float* src = rpe + (size_t)t * TABN;
    float* dst = g_TAB + (size_t)t * TABP;
    #pragma unroll
    for (int k = 0; k < 16; ++k) {
        int i = q*4096 + k*256 + threadIdx.x;
        dst[i] = (i < TABN) ? src[i] : 0.f;
    }
}

// ============================================================================
// Kernel A: q = pq_w @ x[:, :64] + pq_b      (3 blocks; blk0<-x1, blk1/2<-x2)
// grid = 384 (3 blk * 8 b * 16 hw-tiles of 256), 256 threads, 1 hw per thread
// ============================================================================
__global__ __launch_bounds__(256) void k_qproj(
    const float* __restrict__ x1, const float* __restrict__ x2,
    const float* __restrict__ pqw, const float* __restrict__ pqb)
{
    __shared__ float wsT[64*64];  // wsT[c][o] = w[o][c]
    __shared__ float bs[64];
    int bx = blockIdx.x;
    int tile = bx & 15, b = (bx >> 4) & 7, blk = bx >> 7;
    const float* xin = (blk == 0 ? x1 : x2) + (size_t)b * 128 * HWQ;

    for (int i = threadIdx.x; i < 4096; i += 256) {
        int c = i >> 6, o = i & 63;
        wsT[c*64 + o] = pqw[blk*4096 + o*64 + c];
    }
    if (threadIdx.x < 64) bs[threadIdx.x] = pqb[blk*64 + threadIdx.x];
    __syncthreads();

    int hw = tile*256 + threadIdx.x;
    float* qout = g_Q + (size_t)(blk*BD + b) * NCH * HWQ;

    float acc[64];
    #pragma unroll
    for (int o = 0; o < 64; ++o) acc[o] = bs[o];
    #pragma unroll 2
    for (int c = 0; c < 64; ++c) {
        float xv = __ldg(&xin[c*HWQ + hw]);
        const float4* wr = reinterpret_cast<const float4*>(&wsT[c*64]);
        #pragma unroll
        for (int o4 = 0; o4 < 16; ++o4) {
            float4 w = wr[o4];
            acc[o4*4+0] = fmaf(w.x, xv, acc[o4*4+0]);
            acc[o4*4+1] = fmaf(w.y, xv, acc[o4*4+1]);
            acc[o4*4+2] = fmaf(w.z, xv, acc[o4*4+2]);
            acc[o4*4+3] = fmaf(w.w, xv, acc[o4*4+3]);
        }
    }
    #pragma unroll
    for (int o = 0; o < 64; ++o) qout[o*HWQ + hw] = acc[o];
}

// ============================================================================
// Kernel BC: offset head (dwconv4s4 -> LN -> GELU -> 1x1 -> 2ch) -> pos ->
//            deformable gather of kv -> k/v projections + bias params.
// grid = 24 (blk,b), 256 threads = one per key point n=(oy,ox)
// ============================================================================
__global__ __launch_bounds__(256) void k_offkv(
    const float* __restrict__ x0, const float* __restrict__ x1,
    const float* __restrict__ dww, const float* __restrict__ dwb,
    const float* __restrict__ lng, const float* __restrict__ lnb,
    const float* __restrict__ pww,
    const float* __restrict__ pkw, const float* __restrict__ pkb,
    const float* __restrict__ pvw, const float* __restrict__ pvb)
{
    extern __shared__ float sm[];
    float* buf = sm;              // [256][65] (pad 65 -> conflict-free per-row)
    float* skw = sm + 256*65;     // 4096
    float* svw = skw + 4096;      // 4096

    int bx = blockIdx.x;
    int b = bx & 7, blk = bx >> 3;
    const float* kvsrc = (blk == 2 ? x1 : x0) + (size_t)b * 128 * HWQ;
    const float* qsrc  = g_Q + (size_t)(blk*BD + b) * NCH * HWQ;
    int tid = threadIdx.x;

    for (int i = tid; i < 4096; i += 256) {
        skw[i] = pkw[blk*4096 + i];
        svw[i] = pvw[blk*4096 + i];
    }
    __syncthreads();

    int oy = tid >> 4, ox = tid & 15;

    // --- depthwise conv 4x4 stride 4 (VALID) on q plane ---
    float s1 = 0.f, s2 = 0.f;
    const float* wdw = dww + blk * NCH * 16;
    for (int c = 0; c < 64; ++c) {
        float a = __ldg(&dwb[blk*64 + c]);
        const float* qp = qsrc + c*HWQ + (oy*4)*64 + ox*4;
        #pragma unroll
        for (int ky = 0; ky < 4; ++ky)
            #pragma unroll
            for (int kx = 0; kx < 4; ++kx)
                a = fmaf(qp[ky*64 + kx], __ldg(&wdw[c*16 + ky*4 + kx]), a);
        buf[tid*65 + c] = a;
        s1 += a; s2 += a*a;
    }
    float mu  = s1 * (1.f/64.f);
    float var = s2 * (1.f/64.f) - mu*mu;
    float rs  = rsqrtf(var + 1e-5f);

    // --- LN -> exact GELU -> 1x1 to 2 channels (y,x offset) ---
    float offy = 0.f, offx = 0.f;
    for (int c = 0; c < 64; ++c) {
        float v = (buf[tid*65 + c] - mu) * rs * __ldg(&lng[blk*64 + c]) + __ldg(&lnb[blk*64 + c]);
        float gl = 0.5f * v * (1.f + erff(v * 0.70710678118654752f));
        offy = fmaf(__ldg(&pww[blk*128 + c]),      gl, offy);
        offx = fmaf(__ldg(&pww[blk*128 + 64 + c]), gl, offx);
    }
    float refy = (2.f*((float)oy + 0.5f)) * (1.f/15.f) - 1.f;
    float refx = (2.f*((float)ox + 0.5f)) * (1.f/15.f) - 1.f;
    float py = fminf(fmaxf(offy + refy, -1.f), 1.f);
    float px = fminf(fmaxf(offx + refx, -1.f), 1.f);

    // --- bias bilinear params (weights depend only on n) ---
    float ay = 31.5f*(1.f - py), ax = 31.5f*(1.f - px);
    float by0 = floorf(ay), bx0 = floorf(ax);
    g_BP[(blk*BD + b)*NS + tid] = make_float4(by0*127.f + bx0, ay - by0, ax - bx0, 0.f);

    // --- deformable bilinear gather of kv at pos (align_corners=True) ---
    float sy = (py + 1.f)*31.5f, sx = (px + 1.f)*31.5f;
    float fy = floorf(sy), fx = floorf(sx);
    int iy0 = (int)fy, ix0 = (int)fx;
    float wby = sy - fy, wbx = sx - fx;
    int iy1 = min(iy0 + 1, 63), ix1 = min(ix0 + 1, 63);
    float w00 = (1.f-wby)*(1.f-wbx), w01 = (1.f-wby)*wbx;
    float w10 = wby*(1.f-wbx),       w11 = wby*wbx;
    for (int c = 0; c < 64; ++c) {
        const float* ip = kvsrc + c*HWQ;
        float v = w00*ip[iy0*64 + ix0] + w01*ip[iy0*64 + ix1]
                + w10*ip[iy1*64 + ix0] + w11*ip[iy1*64 + ix1];
        buf[tid*65 + c] = v;
    }

    // --- k/v projections ---
    float* kout = g_K + (size_t)(blk*BD + b) * NCH * NS;
    float* vout = g_V + (size_t)(blk*BD + b) * NCH * NS;
    for (int o = 0; o < 64; ++o) {
        float ak = __ldg(&pkb[blk*64 + o]);
        float av = __ldg(&pvb[blk*64 + o]);
        #pragma unroll 8
        for (int c = 0; c < 64; ++c) {
            float xv = buf[tid*65 + c];
            ak = fmaf(skw[o*64 + c], xv, ak);
            av = fmaf(svw[o*64 + c], xv, av);
        }
        kout[o*NS + tid] = ak;
        vout[o*NS + tid] = av;
    }
}

// ============================================================================
// Kernel D: attention. One CTA per (blk,b,head,m-tile of 256). 256 threads,
// one query row m per thread. RPE bias read from padded global tables (L1-hot,
// coalesced since consecutive m -> consecutive columns). smem only K/V/params.
// ============================================================================
__global__ __launch_bounds__(256) void k_attn()
{
    extern __shared__ float sm[];
    float*  Ks    = sm;                          // 256*16, [n][c]
    float*  Vs    = Ks + 4096;                   // 256*16
    int*    pbase = (int*)(Vs + 4096);           // 256
    float4* pw4   = (float4*)(pbase + 256);      // 256

    int bx = blockIdx.x;
    int mt = bx & 15, head = (bx >> 4) & 3, bb = bx >> 6;  // bb = blk*8+b
    int tid = threadIdx.x;

    const float* tab = g_TAB + (size_t)((bb >> 3)*4 + head) * TABP;

    // K/V head slices -> [n][c] float4-friendly layout
    const float* kg = g_K + (size_t)(bb*NCH + head*HCD) * NS;
    const float* vg = g_V + (size_t)(bb*NCH + head*HCD) * NS;
    #pragma unroll
    for (int c4 = 0; c4 < 4; ++c4) {
        float a0 = kg[(c4*4+0)*NS + tid], a1 = kg[(c4*4+1)*NS + tid];
        float a2 = kg[(c4*4+2)*NS + tid], a3 = kg[(c4*4+3)*NS + tid];
        reinterpret_cast<float4*>(Ks)[tid*4 + c4] = make_float4(a0,a1,a2,a3);
        a0 = vg[(c4*4+0)*NS + tid]; a1 = vg[(c4*4+1)*NS + tid];
        a2 = vg[(c4*4+2)*NS + tid]; a3 = vg[(c4*4+3)*NS + tid];
        reinterpret_cast<float4*>(Vs)[tid*4 + c4] = make_float4(a0,a1,a2,a3);
    }
    {
        float4 bp = g_BP[bb*NS + tid];
        pbase[tid] = (int)bp.x;
        float wy = bp.y, wx = bp.z;
        pw4[tid] = make_float4((1.f-wy)*(1.f-wx), (1.f-wy)*wx, wy*(1.f-wx), wy*wx);
    }
    __syncthreads();

    int m = mt*256 + tid;
    int rbase = (m >> 6)*127 + (m & 63);
    const float* qg = g_Q + (size_t)(bb*NCH + head*HCD) * HWQ + m;
    float q[16];
    #pragma unroll
    for (int c = 0; c < 16; ++c) q[c] = qg[c*HWQ];

    float acc[16];
    #pragma unroll
    for (int c = 0; c < 16; ++c) acc[c] = 0.f;
    float ssum = 0.f;

    const float4* Ks4 = (const float4*)Ks;
    const float4* Vs4 = (const float4*)Vs;

    #pragma unroll 4
    for (int n = 0; n < 256; ++n) {
        int o = pbase[n] + rbase;
        float4 w = pw4[n];
        float bias =        w.x * __ldg(&tab[o]);
        bias = fmaf(w.y, __ldg(&tab[o+1]),   bias);
        bias = fmaf(w.z, __ldg(&tab[o+127]), bias);
        bias = fmaf(w.w, __ldg(&tab[o+128]), bias);

        float4 k0 = Ks4[n*4+0], k1 = Ks4[n*4+1], k2 = Ks4[n*4+2], k3 = Ks4[n*4+3];
        float d0 = q[0]*k0.x;  d0 = fmaf(q[1], k0.y, d0);
        d0 = fmaf(q[2], k0.z, d0);  d0 = fmaf(q[3],  k0.w, d0);
        d0 = fmaf(q[4], k1.x, d0);  d0 = fmaf(q[5],  k1.y, d0);
        d0 = fmaf(q[6], k1.z, d0);  d0 = fmaf(q[7],  k1.w, d0);
        float d1 = q[8]*k2.x;  d1 = fmaf(q[9], k2.y, d1);
        d1 = fmaf(q[10], k2.z, d1); d1 = fmaf(q[11], k2.w, d1);
        d1 = fmaf(q[12], k3.x, d1); d1 = fmaf(q[13], k3.y, d1);
        d1 = fmaf(q[14], k3.z, d1); d1 = fmaf(q[15], k3.w, d1);

        float p = __expf(fmaf(d0 + d1, 0.25f, bias));
        ssum += p;

        float4 v0 = Vs4[n*4+0], v1 = Vs4[n*4+1], v2 = Vs4[n*4+2], v3 = Vs4[n*4+3];
        acc[0]  = fmaf(p, v0.x, acc[0]);  acc[1]  = fmaf(p, v0.y, acc[1]);
        acc[2]  = fmaf(p, v0.z, acc[2]);  acc[3]  = fmaf(p, v0.w, acc[3]);
        acc[4]  = fmaf(p, v1.x, acc[4]);  acc[5]  = fmaf(p, v1.y, acc[5]);
        acc[6]  = fmaf(p, v1.z, acc[6]);  acc[7]  = fmaf(p, v1.w, acc[7]);
        acc[8]  = fmaf(p, v2.x, acc[8]);  acc[9]  = fmaf(p, v2.y, acc[9]);
        acc[10] = fmaf(p, v2.z, acc[10]); acc[11] = fmaf(p, v2.w, acc[11]);
        acc[12] = fmaf(p, v3.x, acc[12]); acc[13] = fmaf(p, v3.y, acc[13]);
        acc[14] = fmaf(p, v3.z, acc[14]); acc[15] = fmaf(p, v3.w, acc[15]);
    }

    float inv = 1.f / ssum;
    float* og = g_O + (size_t)(bb*NCH + head*HCD) * HWQ + m;
    #pragma unroll
    for (int c = 0; c < 16; ++c) og[c*HWQ] = acc[c] * inv;
}

// ============================================================================
// Kernel E: final assembly. grid = 384 (3 lvl * 8 b * 16 hw-tiles of 256),
// 256 threads, 1 hw per thread, acc[64] scalar.
// ============================================================================
__global__ __launch_bounds__(256) void k_out(
    const float* __restrict__ x0, const float* __restrict__ x1,
    const float* __restrict__ x2,
    const float* __restrict__ poww, const float* __restrict__ pob,
    float* __restrict__ out)
{
    __shared__ float wsT[2][64*64];  // transposed po weights, up to 2 blocks
    __shared__ float bsum[64];
    int bx = blockIdx.x;
    int tile = bx & 15, b = (bx >> 4) & 7, lvl = bx >> 7;
    const float* xl = (lvl == 0 ? x0 : (lvl == 1 ? x1 : x2)) + (size_t)b * 128 * HWQ;
    float* outp = out + (size_t)(lvl*BD + b) * 128 * HWQ;
    int hw = tile*256 + threadIdx.x;

    // passthrough: channels 0..63
    #pragma unroll 4
    for (int c = 0; c < 64; ++c)
        outp[c*HWQ + hw] = __ldg(&xl[c*HWQ + hw]);

    if (lvl == 0) {
        #pragma unroll 4
        for (int c = 64; c < 128; ++c)
            outp[c*HWQ + hw] = __ldg(&xl[c*HWQ + hw]);
        return;
    }

    int blk0 = (lvl == 1) ? 0 : 1;
    int nb   = (lvl == 1) ? 1 : 2;

    for (int i = threadIdx.x; i < 4096; i += 256) {
        int c = i >> 6, o = i & 63;
        wsT[0][c*64 + o] = poww[blk0*4096 + o*64 + c];
        if (nb == 2) wsT[1][c*64 + o] = poww[(blk0+1)*4096 + o*64 + c];
    }
    if (threadIdx.x < 64) {
        float s = pob[blk0*64 + threadIdx.x];
        if (nb == 2) s += pob[(blk0+1)*64 + threadIdx.x];
        bsum[threadIdx.x] = s;
    }
    __syncthreads();

    const float* o0 = g_O + (size_t)(blk0*BD + b) * NCH * HWQ;
    const float* o1 = g_O + (size_t)((blk0+1)*BD + b) * NCH * HWQ;

    float acc[64];
    #pragma unroll
    for (int o = 0; o < 64; ++o)
        acc[o] = __ldg(&xl[(64 + o)*HWQ + hw]) + bsum[o];

    #pragma unroll 2
    for (int c = 0; c < 64; ++c) {
        float a0 = o0[c*HWQ + hw];
        const float4* wr = reinterpret_cast<const float4*>(&wsT[0][c*64]);
        #pragma unroll
        for (int o4 = 0; o4 < 16; ++o4) {
            float4 w = wr[o4];
            acc[o4*4+0] = fmaf(w.x, a0, acc[o4*4+0]);
            acc[o4*4+1] = fmaf(w.y, a0, acc[o4*4+1]);
            acc[o4*4+2] = fmaf(w.z, a0, acc[o4*4+2]);
            acc[o4*4+3] = fmaf(w.w, a0, acc[o4*4+3]);
        }
    }
    if (nb == 2) {
        #pragma unroll 2
        for (int c = 0; c < 64; ++c) {
            float a1 = o1[c*HWQ + hw];
            const float4* wr = reinterpret_cast<const float4*>(&wsT[1][c*64]);
            #pragma unroll
            for (int o4 = 0; o4 < 16; ++o4) {
                float4 w = wr[o4];
                acc[o4*4+0] = fmaf(w.x, a1, acc[o4*4+0]);
                acc[o4*4+1] = fmaf(w.y, a1, acc[o4*4+1]);
                acc[o4*4+2] = fmaf(w.z, a1, acc[o4*4+2]);
                acc[o4*4+3] = fmaf(w.w, a1, acc[o4*4+3]);
            }
        }
    }
    #pragma unroll
    for (int o = 0; o < 64; ++o)
        outp[(64 + o)*HWQ + hw] = acc[o];
}

// ============================================================================
extern "C" void kernel_launch(void* const* d_in, const int* in_sizes, int n_in,
                              void* d_out, int out_size)
{
    const float* x0  = (const float*)d_in[0];
    const float* x1  = (const float*)d_in[1];
    const float* x2  = (const float*)d_in[2];
    const float* pqw = (const float*)d_in[3];
    const float* pqb = (const float*)d_in[4];
    const float* dww = (const float*)d_in[5];
    const float* dwb = (const float*)d_in[6];
    const float* lng = (const float*)d_in[7];
    const float* lnb = (const float*)d_in[8];
    const float* pww = (const float*)d_in[9];
    const float* pkw = (const float*)d_in[10];
    const float* pkb = (const float*)d_in[11];
    const float* pvw = (const float*)d_in[12];
    const float* pvb = (const float*)d_in[13];
    const float* pow_ = (const float*)d_in[14];
    const float* pob = (const float*)d_in[15];
    const float* rpe = (const float*)d_in[16];

    const int bc_smem = (256*65 + 4096 + 4096) * 4;        // 99328 B
    const int d_smem  = (4096 + 4096) * 4 + 256*4 + 256*16; // 37888 B
    cudaFuncSetAttribute(k_offkv, cudaFuncAttributeMaxDynamicSharedMemorySize, bc_smem);
    cudaFuncSetAttribute(k_attn,  cudaFuncAttributeMaxDynamicSharedMemorySize, d_smem);

    k_tab<<<48, 256>>>(rpe);
    k_qproj<<<384, 256>>>(x1, x2, pqw, pqb);
    k_offkv<<<24, 256, bc_smem>>>(x0, x1, dww, dwb, lng, lnb, pww,
                                  pkw, pkb, pvw, pvb);
    k_attn<<<1536, 256, d_smem>>>();
    k_out<<<384, 256>>>(x0, x1, x2, pow_, pob, (float*)d_out);
}

// round 4
// speedup vs baseline: 1.3755x; 1.2818x over previous
#include <cuda_runtime.h>
#include <math.h>

#define NBLK 3
#define BD 8
#define HWQ 4096   // 64*64
#define NCH 64     // NC (channels per DAT block)
#define NS  256    // Hk*Wk = 16*16
#define HCD 16     // head channels
#define TABN 16129 // 127*127
#define TABP 16384 // padded dual-table stride

// ---- static device scratch (no runtime allocation allowed) ----
__device__ float  g_Q[NBLK*BD*NCH*HWQ];   // q projections      [blk][b][c][hw]
__device__ float  g_O[NBLK*BD*NCH*HWQ];   // attention outputs  [blk][b][c][hw]
__device__ float  g_K[NBLK*BD*NCH*NS];    // keys   [blk][b][c][n]
__device__ float  g_V[NBLK*BD*NCH*NS];    // values [blk][b][c][n]
__device__ float4 g_BP[NBLK*BD*NS];       // bias params per n: (y0*127+x0, wy, wx, 0)
__device__ float2 g_POS[NBLK*BD*NS];      // normalized sample pos (py,px)
__device__ float  g_DW[NBLK*BD*NCH*NS];   // dwconv output [blk][b][c][n]
__device__ float2 g_TAB2[NBLK*4*TABP];    // dual RPE tables: (t[i], t[i+1]), zero-padded

// ============================================================================
// Kernel T: build dual tables. grid = 12 tables * 8 chunks = 96
// ============================================================================
__global__ __launch_bounds__(256) void k_tab2(const float* __restrict__ rpe)
{
    int t = blockIdx.x >> 3, q = blockIdx.x & 7;
    const float* src = rpe + (size_t)t * TABN;
    float2* dst = g_TAB2 + (size_t)t * TABP;
    #pragma unroll
    for (int k = 0; k < 8; ++k) {
        int i = q*2048 + k*256 + threadIdx.x;
        float a = (i < TABN)     ? src[i]   : 0.f;
        float b = (i+1 < TABN)   ? src[i+1] : 0.f;
        dst[i] = make_float2(a, b);
    }
}

// ============================================================================
// Kernel A: q = pq_w @ x[:, :64] + pq_b      (3 blocks; blk0<-x1, blk1/2<-x2)
// grid = 384 (3 blk * 8 b * 16 hw-tiles of 256), 256 threads, 1 hw per thread
// ============================================================================
__global__ __launch_bounds__(256) void k_qproj(
    const float* __restrict__ x1, const float* __restrict__ x2,
    const float* __restrict__ pqw, const float* __restrict__ pqb)
{
    __shared__ float wsT[64*64];  // wsT[c][o] = w[o][c]
    __shared__ float bs[64];
    int bx = blockIdx.x;
    int tile = bx & 15, b = (bx >> 4) & 7, blk = bx >> 7;
    const float* xin = (blk == 0 ? x1 : x2) + (size_t)b * 128 * HWQ;

    for (int i = threadIdx.x; i < 4096; i += 256) {
        int c = i >> 6, o = i & 63;
        wsT[c*64 + o] = pqw[blk*4096 + o*64 + c];
    }
    if (threadIdx.x < 64) bs[threadIdx.x] = pqb[blk*64 + threadIdx.x];
    __syncthreads();

    int hw = tile*256 + threadIdx.x;
    float* qout = g_Q + (size_t)(blk*BD + b) * NCH * HWQ;

    float acc[64];
    #pragma unroll
    for (int o = 0; o < 64; ++o) acc[o] = bs[o];
    #pragma unroll 2
    for (int c = 0; c < 64; ++c) {
        float xv = __ldg(&xin[c*HWQ + hw]);
        const float4* wr = reinterpret_cast<const float4*>(&wsT[c*64]);
        #pragma unroll
        for (int o4 = 0; o4 < 16; ++o4) {
            float4 w = wr[o4];
            acc[o4*4+0] = fmaf(w.x, xv, acc[o4*4+0]);
            acc[o4*4+1] = fmaf(w.y, xv, acc[o4*4+1]);
            acc[o4*4+2] = fmaf(w.z, xv, acc[o4*4+2]);
            acc[o4*4+3] = fmaf(w.w, xv, acc[o4*4+3]);
        }
    }
    #pragma unroll
    for (int o = 0; o < 64; ++o) qout[o*HWQ + hw] = acc[o];
}

// ============================================================================
// Kernel B1: depthwise conv 4x4 s4 on q plane, smem-staged (coalesced).
// grid = 384 (3 blk * 8 b * 16 c-chunks of 4ch), 256 threads (one per n)
// ============================================================================
__global__ __launch_bounds__(256) void k_dw(
    const float* __restrict__ dww, const float* __restrict__ dwb)
{
    __shared__ float sq[4*HWQ];   // 4 channels of the q plane (64 KB)
    int bx = blockIdx.x;
    int cchunk = bx & 15, b = (bx >> 4) & 7, blk = bx >> 7;
    int c0 = cchunk * 4;
    int tid = threadIdx.x;
    const float* qsrc = g_Q + ((size_t)(blk*BD + b)*NCH + c0) * HWQ;

    for (int i = tid; i < 4096; i += 256)
        reinterpret_cast<float4*>(sq)[i] = reinterpret_cast<const float4*>(qsrc)[i];
    __syncthreads();

    int oy = tid >> 4, ox = tid & 15;
    float* dwp = g_DW + ((size_t)(blk*BD + b)*NCH + c0) * NS;
    #pragma unroll
    for (int cc = 0; cc < 4; ++cc) {
        int c = c0 + cc;
        float a = __ldg(&dwb[blk*64 + c]);
        const float* w = dww + blk*NCH*16 + c*16;
        const float* sp = sq + cc*HWQ + oy*256 + ox*4;
        #pragma unroll
        for (int ky = 0; ky < 4; ++ky)
            #pragma unroll
            for (int kx = 0; kx < 4; ++kx)
                a = fmaf(sp[ky*64 + kx], __ldg(&w[ky*4 + kx]), a);
        dwp[cc*NS + tid] = a;
    }
}

// ============================================================================
// Kernel B2: LN (per-point over channels -> thread-local) -> GELU -> 1x1 ->
//            offsets -> pos + bias params. grid = 24, 256 threads (one per n)
// ============================================================================
__global__ __launch_bounds__(256) void k_off2(
    const float* __restrict__ lng, const float* __restrict__ lnb,
    const float* __restrict__ pww)
{
    int bx = blockIdx.x;
    int b = bx & 7, blk = bx >> 3;
    int n = threadIdx.x;
    int oy = n >> 4, ox = n & 15;
    const float* dwp = g_DW + (size_t)(blk*BD + b)*NCH*NS;

    float v[64];
    float s1 = 0.f, s2 = 0.f;
    #pragma unroll
    for (int c = 0; c < 64; ++c) {
        float a = dwp[c*NS + n];
        v[c] = a; s1 += a; s2 += a*a;
    }
    float mu  = s1 * (1.f/64.f);
    float var = s2 * (1.f/64.f) - mu*mu;
    float rs  = rsqrtf(var + 1e-5f);

    float offy = 0.f, offx = 0.f;
    #pragma unroll 4
    for (int c = 0; c < 64; ++c) {
        float t = (v[c] - mu) * rs * __ldg(&lng[blk*64 + c]) + __ldg(&lnb[blk*64 + c]);
        float gl = 0.5f * t * (1.f + erff(t * 0.70710678118654752f));
        offy = fmaf(__ldg(&pww[blk*128 + c]),      gl, offy);
        offx = fmaf(__ldg(&pww[blk*128 + 64 + c]), gl, offx);
    }
    float refy = (2.f*((float)oy + 0.5f)) * (1.f/15.f) - 1.f;
    float refx = (2.f*((float)ox + 0.5f)) * (1.f/15.f) - 1.f;
    float py = fminf(fmaxf(offy + refy, -1.f), 1.f);
    float px = fminf(fmaxf(offx + refx, -1.f), 1.f);

    float ay = 31.5f*(1.f - py), ax = 31.5f*(1.f - px);
    float by0 = floorf(ay), bx0 = floorf(ax);
    g_BP[(blk*BD + b)*NS + n]  = make_float4(by0*127.f + bx0, ay - by0, ax - bx0, 0.f);
    g_POS[(blk*BD + b)*NS + n] = make_float2(py, px);
}

// ============================================================================
// Kernel B3: deformable gather + k/v projections.
// grid = 96 (3 blk * 8 b * 4 n-chunks of 64), 256 threads = (nl 64, cg 4)
// ============================================================================
__global__ __launch_bounds__(256) void k_gkv(
    const float* __restrict__ x0, const float* __restrict__ x1,
    const float* __restrict__ pkw, const float* __restrict__ pkb,
    const float* __restrict__ pvw, const float* __restrict__ pvb)
{
    extern __shared__ float sm[];
    float* buf = sm;              // [64][65]
    float* skw = sm + 64*65;      // 4096
    float* svw = skw + 4096;      // 4096

    int bx = blockIdx.x;
    int nc = bx & 3, b = (bx >> 2) & 7, blk = bx >> 5;
    const float* kvsrc = (blk == 2 ? x1 : x0) + (size_t)b * 128 * HWQ;
    int tid = threadIdx.x;
    int nl = tid & 63, cg = tid >> 6;
    int n = nc*64 + nl;

    for (int i = tid; i < 4096; i += 256) {
        skw[i] = pkw[blk*4096 + i];
        svw[i] = pvw[blk*4096 + i];
    }

    float2 pos = g_POS[(blk*BD + b)*NS + n];
    float sy = (pos.x + 1.f)*31.5f, sx = (pos.y + 1.f)*31.5f;
    float fy = floorf(sy), fx = floorf(sx);
    int iy0 = (int)fy, ix0 = (int)fx;
    float wby = sy - fy, wbx = sx - fx;
    int iy1 = min(iy0 + 1, 63), ix1 = min(ix0 + 1, 63);
    float w00 = (1.f-wby)*(1.f-wbx), w01 = (1.f-wby)*wbx;
    float w10 = wby*(1.f-wbx),       w11 = wby*wbx;
    #pragma unroll 4
    for (int cc = 0; cc < 16; ++cc) {
        int c = cg*16 + cc;
        const float* ip = kvsrc + c*HWQ;
        float val = w00*__ldg(&ip[iy0*64 + ix0]) + w01*__ldg(&ip[iy0*64 + ix1])
                  + w10*__ldg(&ip[iy1*64 + ix0]) + w11*__ldg(&ip[iy1*64 + ix1]);
        buf[nl*65 + c] = val;
    }
    __syncthreads();

    float* kout = g_K + (size_t)(blk*BD + b)*NCH*NS;
    float* vout = g_V + (size_t)(blk*BD + b)*NCH*NS;
    #pragma unroll 2
    for (int oo = 0; oo < 16; ++oo) {
        int o = cg*16 + oo;
        float ak = __ldg(&pkb[blk*64 + o]);
        float av = __ldg(&pvb[blk*64 + o]);
        #pragma unroll 8
        for (int c = 0; c < 64; ++c) {
            float xv = buf[nl*65 + c];
            ak = fmaf(skw[o*64 + c], xv, ak);
            av = fmaf(svw[o*64 + c], xv, av);
        }
        kout[o*NS + n] = ak;
        vout[o*NS + n] = av;
    }
}

// ============================================================================
// Kernel D: attention. One CTA per (blk,b,head,row-tile of 8). 256 threads,
// each thread = vertical query PAIR (rows y,y+1, column x): K/V/params LDS
// amortized 2x, bias taps via dual float2 table (3 LDG.64 per pair-iter).
// ============================================================================
__global__ __launch_bounds__(256, 2) void k_attn()
{
    extern __shared__ float sm[];
    float*  Ks  = sm;                          // 256*16, [n][c]
    float*  Vs  = Ks + 4096;                   // 256*16
    float4* pp4 = (float4*)(Vs + 4096);        // 256: (w00,w01,w10, base)

    int bx = blockIdx.x;
    int tile = bx & 7, head = (bx >> 3) & 3, bb = bx >> 5;  // bb = blk*8+b
    int tid = threadIdx.x;

    const float2* tab = g_TAB2 + (size_t)((bb >> 3)*4 + head) * TABP;

    const float* kg = g_K + (size_t)(bb*NCH + head*HCD) * NS;
    const float* vg = g_V + (size_t)(bb*NCH + head*HCD) * NS;
    #pragma unroll
    for (int c4 = 0; c4 < 4; ++c4) {
        float a0 = kg[(c4*4+0)*NS + tid], a1 = kg[(c4*4+1)*NS + tid];
        float a2 = kg[(c4*4+2)*NS + tid], a3 = kg[(c4*4+3)*NS + tid];
        reinterpret_cast<float4*>(Ks)[tid*4 + c4] = make_float4(a0,a1,a2,a3);
        a0 = vg[(c4*4+0)*NS + tid]; a1 = vg[(c4*4+1)*NS + tid];
        a2 = vg[(c4*4+2)*NS + tid]; a3 = vg[(c4*4+3)*NS + tid];
        reinterpret_cast<float4*>(Vs)[tid*4 + c4] = make_float4(a0,a1,a2,a3);
    }
    {
        float4 bp = g_BP[bb*NS + tid];
        float wy = bp.y, wx = bp.z;
        pp4[tid] = make_float4((1.f-wy)*(1.f-wx), (1.f-wy)*wx, wy*(1.f-wx), bp.x);
    }
    __syncthreads();

    int x = tid & 63, yp = tid >> 6;
    int y = tile*8 + yp*2;
    int m1 = y*64 + x;                 // m2 = m1 + 64 (row y+1)
    int rbase = y*127 + x;
    const float* qg = g_Q + (size_t)(bb*NCH + head*HCD) * HWQ;
    float q1[16], q2[16];
    #pragma unroll
    for (int c = 0; c < 16; ++c) {
        q1[c] = qg[c*HWQ + m1];
        q2[c] = qg[c*HWQ + m1 + 64];
    }

    float acc1[16], acc2[16];
    #pragma unroll
    for (int c = 0; c < 16; ++c) { acc1[c] = 0.f; acc2[c] = 0.f; }
    float ss1 = 0.f, ss2 = 0.f;

    const float4* Ks4 = (const float4*)Ks;
    const float4* Vs4 = (const float4*)Vs;

    #pragma unroll 2
    for (int n = 0; n < 256; ++n) {
        float4 pp = pp4[n];
        int o = (int)pp.w + rbase;
        float w11 = 1.f - pp.x - pp.y - pp.z;
        float2 t0 = __ldg(&tab[o]);
        float2 t1 = __ldg(&tab[o + 127]);
        float2 t2 = __ldg(&tab[o + 254]);
        float b1 = pp.x * t0.x;
        b1 = fmaf(pp.y, t0.y, b1); b1 = fmaf(pp.z, t1.x, b1); b1 = fmaf(w11, t1.y, b1);
        float b2 = pp.x * t1.x;
        b2 = fmaf(pp.y, t1.y, b2); b2 = fmaf(pp.z, t2.x, b2); b2 = fmaf(w11, t2.y, b2);

        float4 k0 = Ks4[n*4+0], k1 = Ks4[n*4+1], k2 = Ks4[n*4+2], k3 = Ks4[n*4+3];
        float d1 = q1[0]*k0.x;
        d1 = fmaf(q1[1], k0.y, d1); d1 = fmaf(q1[2],  k0.z, d1); d1 = fmaf(q1[3],  k0.w, d1);
        d1 = fmaf(q1[4], k1.x, d1); d1 = fmaf(q1[5],  k1.y, d1); d1 = fmaf(q1[6],  k1.z, d1);
        d1 = fmaf(q1[7], k1.w, d1); d1 = fmaf(q1[8],  k2.x, d1); d1 = fmaf(q1[9],  k2.y, d1);
        d1 = fmaf(q1[10],k2.z, d1); d1 = fmaf(q1[11], k2.w, d1); d1 = fmaf(q1[12], k3.x, d1);
        d1 = fmaf(q1[13],k3.y, d1); d1 = fmaf(q1[14], k3.z, d1); d1 = fmaf(q1[15], k3.w, d1);
        float d2 = q2[0]*k0.x;
        d2 = fmaf(q2[1], k0.y, d2); d2 = fmaf(q2[2],  k0.z, d2); d2 = fmaf(q2[3],  k0.w, d2);
        d2 = fmaf(q2[4], k1.x, d2); d2 = fmaf(q2[5],  k1.y, d2); d2 = fmaf(q2[6],  k1.z, d2);
        d2 = fmaf(q2[7], k1.w, d2); d2 = fmaf(q2[8],  k2.x, d2); d2 = fmaf(q2[9],  k2.y, d2);
        d2 = fmaf(q2[10],k2.z, d2); d2 = fmaf(q2[11], k2.w, d2); d2 = fmaf(q2[12], k3.x, d2);
        d2 = fmaf(q2[13],k3.y, d2); d2 = fmaf(q2[14], k3.z, d2); d2 = fmaf(q2[15], k3.w, d2);

        float p1 = __expf(fmaf(d1, 0.25f, b1)); ss1 += p1;
        float p2 = __expf(fmaf(d2, 0.25f, b2)); ss2 += p2;

        float4 v0 = Vs4[n*4+0], v1 = Vs4[n*4+1], v2 = Vs4[n*4+2], v3 = Vs4[n*4+3];
        acc1[0]  = fmaf(p1, v0.x, acc1[0]);  acc2[0]  = fmaf(p2, v0.x, acc2[0]);
        acc1[1]  = fmaf(p1, v0.y, acc1[1]);  acc2[1]  = fmaf(p2, v0.y, acc2[1]);
        acc1[2]  = fmaf(p1, v0.z, acc1[2]);  acc2[2]  = fmaf(p2, v0.z, acc2[2]);
        acc1[3]  = fmaf(p1, v0.w, acc1[3]);  acc2[3]  = fmaf(p2, v0.w, acc2[3]);
        acc1[4]  = fmaf(p1, v1.x, acc1[4]);  acc2[4]  = fmaf(p2, v1.x, acc2[4]);
        acc1[5]  = fmaf(p1, v1.y, acc1[5]);  acc2[5]  = fmaf(p2, v1.y, acc2[5]);
        acc1[6]  = fmaf(p1, v1.z, acc1[6]);  acc2[6]  = fmaf(p2, v1.z, acc2[6]);
        acc1[7]  = fmaf(p1, v1.w, acc1[7]);  acc2[7]  = fmaf(p2, v1.w, acc2[7]);
        acc1[8]  = fmaf(p1, v2.x, acc1[8]);  acc2[8]  = fmaf(p2, v2.x, acc2[8]);
        acc1[9]  = fmaf(p1, v2.y, acc1[9]);  acc2[9]  = fmaf(p2, v2.y, acc2[9]);
        acc1[10] = fmaf(p1, v2.z, acc1[10]); acc2[10] = fmaf(p2, v2.z, acc2[10]);
        acc1[11] = fmaf(p1, v2.w, acc1[11]); acc2[11] = fmaf(p2, v2.w, acc2[11]);
        acc1[12] = fmaf(p1, v3.x, acc1[12]); acc2[12] = fmaf(p2, v3.x, acc2[12]);
        acc1[13] = fmaf(p1, v3.y, acc1[13]); acc2[13] = fmaf(p2, v3.y, acc2[13]);
        acc1[14] = fmaf(p1, v3.z, acc1[14]); acc2[14] = fmaf(p2, v3.z, acc2[14]);
        acc1[15] = fmaf(p1, v3.w, acc1[15]); acc2[15] = fmaf(p2, v3.w, acc2[15]);
    }

    float i1 = 1.f / ss1, i2 = 1.f / ss2;
    float* og = g_O + (size_t)(bb*NCH + head*HCD) * HWQ;
    #pragma unroll
    for (int c = 0; c < 16; ++c) {
        og[c*HWQ + m1]      = acc1[c] * i1;
        og[c*HWQ + m1 + 64] = acc2[c] * i2;
    }
}

// ============================================================================
// Kernel E: final assembly. grid = 384 (3 lvl * 8 b * 16 hw-tiles of 256),
// 256 threads, 1 hw per thread, acc[64] scalar.
// ============================================================================
__global__ __launch_bounds__(256) void k_out(
    const float* __restrict__ x0, const float* __restrict__ x1,
    const float* __restrict__ x2,
    const float* __restrict__ poww, const float* __restrict__ pob,
    float* __restrict__ out)
{
    __shared__ float wsT[2][64*64];
    __shared__ float bsum[64];
    int bx = blockIdx.x;
    int tile = bx & 15, b = (bx >> 4) & 7, lvl = bx >> 7;
    const float* xl = (lvl == 0 ? x0 : (lvl == 1 ? x1 : x2)) + (size_t)b * 128 * HWQ;
    float* outp = out + (size_t)(lvl*BD + b) * 128 * HWQ;
    int hw = tile*256 + threadIdx.x;

    #pragma unroll 4
    for (int c = 0; c < 64; ++c)
        outp[c*HWQ + hw] = __ldg(&xl[c*HWQ + hw]);

    if (lvl == 0) {
        #pragma unroll 4
        for (int c = 64; c < 128; ++c)
            outp[c*HWQ + hw] = __ldg(&xl[c*HWQ + hw]);
        return;
    }

    int blk0 = (lvl == 1) ? 0 : 1;
    int nb   = (lvl == 1) ? 1 : 2;

    for (int i = threadIdx.x; i < 4096; i += 256) {
        int c = i >> 6, o = i & 63;
        wsT[0][c*64 + o] = poww[blk0*4096 + o*64 + c];
        if (nb == 2) wsT[1][c*64 + o] = poww[(blk0+1)*4096 + o*64 + c];
    }
    if (threadIdx.x < 64) {
        float s = pob[blk0*64 + threadIdx.x];
        if (nb == 2) s += pob[(blk0+1)*64 + threadIdx.x];
        bsum[threadIdx.x] = s;
    }
    __syncthreads();

    const float* o0 = g_O + (size_t)(blk0*BD + b) * NCH * HWQ;
    const float* o1 = g_O + (size_t)((blk0+1)*BD + b) * NCH * HWQ;

    float acc[64];
    #pragma unroll
    for (int o = 0; o < 64; ++o)
        acc[o] = __ldg(&xl[(64 + o)*HWQ + hw]) + bsum[o];

    #pragma unroll 2
    for (int c = 0; c < 64; ++c) {
        float a0 = o0[c*HWQ + hw];
        const float4* wr = reinterpret_cast<const float4*>(&wsT[0][c*64]);
        #pragma unroll
        for (int o4 = 0; o4 < 16; ++o4) {
            float4 w = wr[o4];
            acc[o4*4+0] = fmaf(w.x, a0, acc[o4*4+0]);
            acc[o4*4+1] = fmaf(w.y, a0, acc[o4*4+1]);
            acc[o4*4+2] = fmaf(w.z, a0, acc[o4*4+2]);
            acc[o4*4+3] = fmaf(w.w, a0, acc[o4*4+3]);
        }
    }
    if (nb == 2) {
        #pragma unroll 2
        for (int c = 0; c < 64; ++c) {
            float a1 = o1[c*HWQ + hw];
            const float4* wr = reinterpret_cast<const float4*>(&wsT[1][c*64]);
            #pragma unroll
            for (int o4 = 0; o4 < 16; ++o4) {
                float4 w = wr[o4];
                acc[o4*4+0] = fmaf(w.x, a1, acc[o4*4+0]);
                acc[o4*4+1] = fmaf(w.y, a1, acc[o4*4+1]);
                acc[o4*4+2] = fmaf(w.z, a1, acc[o4*4+2]);
                acc[o4*4+3] = fmaf(w.w, a1, acc[o4*4+3]);
            }
        }
    }
    #pragma unroll
    for (int o = 0; o < 64; ++o)
        outp[(64 + o)*HWQ + hw] = acc[o];
}

// ============================================================================
extern "C" void kernel_launch(void* const* d_in, const int* in_sizes, int n_in,
                              void* d_out, int out_size)
{
    const float* x0  = (const float*)d_in[0];
    const float* x1  = (const float*)d_in[1];
    const float* x2  = (const float*)d_in[2];
    const float* pqw = (const float*)d_in[3];
    const float* pqb = (const float*)d_in[4];
    const float* dww = (const float*)d_in[5];
    const float* dwb = (const float*)d_in[6];
    const float* lng = (const float*)d_in[7];
    const float* lnb = (const float*)d_in[8];
    const float* pww = (const float*)d_in[9];
    const float* pkw = (const float*)d_in[10];
    const float* pkb = (const float*)d_in[11];
    const float* pvw = (const float*)d_in[12];
    const float* pvb = (const float*)d_in[13];
    const float* pow_ = (const float*)d_in[14];
    const float* pob = (const float*)d_in[15];
    const float* rpe = (const float*)d_in[16];

    const int gkv_smem = (64*65 + 4096 + 4096) * 4;        // 49408 B
    const int d_smem   = (4096 + 4096) * 4 + 256*16;       // 36864 B
    cudaFuncSetAttribute(k_gkv,  cudaFuncAttributeMaxDynamicSharedMemorySize, gkv_smem);
    cudaFuncSetAttribute(k_attn, cudaFuncAttributeMaxDynamicSharedMemorySize, d_smem);

    k_tab2<<<96, 256>>>(rpe);
    k_qproj<<<384, 256>>>(x1, x2, pqw, pqb);
    k_dw<<<384, 256>>>(dww, dwb);
    k_off2<<<24, 256>>>(lng, lnb, pww);
    k_gkv<<<96, 256, gkv_smem>>>(x0, x1, pkw, pkb, pvw, pvb);
    k_attn<<<768, 256, d_smem>>>();
    k_out<<<384, 256>>>(x0, x1, x2, pow_, pob, (float*)d_out);
}